// round 4
// baseline (speedup 1.0000x reference)
#include <cuda_runtime.h>
#include <math.h>
#include <stdint.h>

#define T_LEN 1000
#define BATCH 32
#define NF 34
#define HDIM 640
#define NB 128            // persistent blocks (5 hidden cols each)

// ------------------------- device scratch (~189 MB total) ------------------
__device__ float d_X2[BATCH * 2 * NF * T_LEN];           // 8.7 MB
__device__ float d_dkw0[HDIM * 14];
__device__ float d_dkw1[HDIM * 14];
__device__ int   d_dklo[HDIM * 14];
__device__ float d_Y[HDIM * BATCH * T_LEN];              // 81.9 MB  [hseq][b][t]
__device__ float d_mean[64];
__device__ float d_rstd[64];
__device__ float d_seq[(size_t)T_LEN * HDIM * BATCH];    // 81.9 MB  [t][k][b]
__device__ float d_hbuf[2][HDIM * BATCH];                // ping-pong h  [k][b]
__device__ float d_fcpart[(size_t)T_LEN * NB * BATCH];   // 16.4 MB

// ------------------------- grid barrier ------------------------------------
__device__ volatile unsigned g_epoch = 0;
__device__ unsigned g_count = 0;

__device__ __forceinline__ void grid_barrier() {
    __syncthreads();
    if (threadIdx.x == 0) {
        unsigned e = g_epoch;
        __threadfence();
        if (atomicAdd(&g_count, 1u) == NB - 1) {
            g_count = 0;
            __threadfence();
            g_epoch = e + 1;
        } else {
            while (g_epoch == e) { }
        }
        __threadfence();
    }
    __syncthreads();
}

// ------------------- K1: truncated EMA highpass + rectify ------------------
__global__ void k1_highpass(const float* __restrict__ x,
                            const float* __restrict__ a_vals,
                            const float* __restrict__ w_vals) {
    int b = blockIdx.x, f = blockIdx.y;
    __shared__ float xs[T_LEN];
    __shared__ float cs[200];
    const float* xr = x + (size_t)(b * NF + f) * T_LEN;
    for (int i = threadIdx.x; i < T_LEN; i += 256) xs[i] = xr[i];
    float a = a_vals[f];
    float w = w_vals[f];
    float l2 = log2f(1.0f - a);
    for (int j = threadIdx.x; j < 200; j += 256) cs[j] = a * exp2f(l2 * (float)j);
    __syncthreads();
    for (int t = threadIdx.x; t < T_LEN; t += 256) {
        float low = 0.f;
        int jm = min(199, t);
        for (int j = 0; j <= jm; ++j) low += cs[j] * xs[t - j];
        float hp = xs[t] - w * low;
        d_X2[((size_t)(b * 2 + 0) * NF + f) * T_LEN + t] = fmaxf(hp, 0.f);
        d_X2[((size_t)(b * 2 + 1) * NF + f) * T_LEN + t] = fmaxf(-hp, 0.f);
    }
}

// ------------------- K2: DCLS triangular kernel -> 2 taps ------------------
__global__ void k2_dk(const float* __restrict__ dcls_w,
                      const float* __restrict__ dcls_p) {
    int idx = blockIdx.x * 256 + threadIdx.x;
    if (idx < HDIM * 14) {
        float p = fminf(fmaxf(dcls_p[idx], 0.f), 8.f);
        float lo = floorf(p);
        float fr = p - lo;
        float w = dcls_w[idx];
        d_dkw0[idx] = w * (1.f - fr);
        d_dkw1[idx] = w * fr;
        d_dklo[idx] = (int)lo;
    }
}

// ------------------- K3: DCLS grouped conv + bias --------------------------
__global__ void k3_dcls(const float* __restrict__ dcls_b) {
    int g = blockIdx.x;     // 0..9
    int b = blockIdx.y;     // 0..31
    extern __shared__ float us[];           // 14 * 1012 floats
    const int P = 1012;
    for (int i = threadIdx.x; i < 14 * P; i += 256) us[i] = 0.f;
    __syncthreads();
    for (int i = 0; i < 14; ++i) {
        int s = i / 7, kk = i % 7;
        const float* src = d_X2 + ((size_t)(b * 2 + s) * NF + g * 3 + kk) * T_LEN;
        for (int t = threadIdx.x; t < T_LEN; t += 256) us[i * P + 4 + t] = src[t];
    }
    __syncthreads();
    for (int c = 0; c < 64; ++c) {
        int h = g * 64 + c;                 // conv channel (group-major)
        float w0[14], w1[14]; int lo[14];
#pragma unroll
        for (int i = 0; i < 14; ++i) {
            w0[i] = d_dkw0[h * 14 + i];
            w1[i] = d_dkw1[h * 14 + i];
            lo[i] = d_dklo[h * 14 + i];
        }
        float bias = dcls_b[h];
        int hseq = c * 10 + g;              // seq feature index
        float* dst = d_Y + ((size_t)hseq * BATCH + b) * T_LEN;
        for (int t = threadIdx.x; t < T_LEN; t += 256) {
            float acc = bias;
#pragma unroll
            for (int i = 0; i < 14; ++i) {
                acc += w0[i] * us[i * P + t + lo[i]];
                acc += w1[i] * us[i * P + t + lo[i] + 1];
            }
            dst[t] = acc;
        }
    }
}

// ------------------- K4: BN stats per channel c ----------------------------
__global__ void k4_stats() {
    int c = blockIdx.x;     // 0..63; hseq in [c*10, c*10+10) is contiguous
    const float* p = d_Y + (size_t)c * 10 * BATCH * T_LEN;
    double s = 0.0, s2 = 0.0;
    for (int i = threadIdx.x; i < 10 * BATCH * T_LEN; i += 256) {
        float v = p[i];
        s += (double)v;
        s2 += (double)v * (double)v;
    }
    __shared__ double sh[256], sh2[256];
    sh[threadIdx.x] = s; sh2[threadIdx.x] = s2;
    __syncthreads();
    for (int o = 128; o > 0; o >>= 1) {
        if (threadIdx.x < o) { sh[threadIdx.x] += sh[threadIdx.x + o]; sh2[threadIdx.x] += sh2[threadIdx.x + o]; }
        __syncthreads();
    }
    if (threadIdx.x == 0) {
        double mean = sh[0] / 320000.0;
        double var = sh2[0] / 320000.0 - mean * mean;
        d_mean[c] = (float)mean;
        d_rstd[c] = (float)(1.0 / sqrt(var + 1e-5));
    }
}

// ------------------- K5: normalize + sigmoid -> seq[t][k][b] ---------------
__global__ void k5_norm(const float* __restrict__ gamma,
                        const float* __restrict__ beta) {
    int h = blockIdx.x;                // 0..639 (= c*10 + g)
    int c = h / 10;
    float m = d_mean[c], r = d_rstd[c], ga = gamma[c], be = beta[c];
    const float* src = d_Y + (size_t)h * BATCH * T_LEN;
    for (int i = threadIdx.x; i < BATCH * T_LEN; i += 256) {
        int b = i & 31, t = i >> 5;
        float v = (src[(size_t)b * T_LEN + t] - m) * r * ga + be;
        float sg = 1.f / (1.f + expf(-v));
        d_seq[(size_t)t * (HDIM * BATCH) + h * BATCH + b] = sg;
    }
}

// ------------------- K6: persistent fused GRU (ih + hh matvecs) ------------
// SMEM (floats): hs[640*32] staging (seq[t] then h) | wih[640*16] | whh[640*16]
//                xacc[2*16*32] | gacc[2*16*32] | hn[5*32] | bih[16] | bhh[16] | fcw[8]
#define SM_HS   0
#define SM_WIH  (SM_HS + HDIM * BATCH)          // 20480
#define SM_WHH  (SM_WIH + HDIM * 16)            // +10240
#define SM_XACC (SM_WHH + HDIM * 16)            // +10240
#define SM_GACC (SM_XACC + 2 * 16 * 32)         // +1024
#define SM_HN   (SM_GACC + 2 * 16 * 32)         // +1024
#define SM_BIH  (SM_HN + 5 * 32)
#define SM_BHH  (SM_BIH + 16)
#define SM_FCW  (SM_BHH + 16)
#define SM6_FLOATS (SM_FCW + 8)                 // 43208 floats = 172,832 B

__device__ __forceinline__ void matvec_16x32(const float* __restrict__ vec,
                                             const float* __restrict__ wmat,
                                             float* __restrict__ acc,
                                             int kh, int rg, int lane) {
    const int kb = kh * 320;
    const float* hp = vec + kb * 32 + lane;
    const float* wp = wmat + kb * 16 + (rg << 2);
    float a0 = 0.f, a1 = 0.f, a2 = 0.f, a3 = 0.f;
#pragma unroll 8
    for (int kk = 0; kk < 320; ++kk) {
        float hv = hp[kk * 32];
        float4 w = *(const float4*)(wp + kk * 16);
        a0 += w.x * hv; a1 += w.y * hv; a2 += w.z * hv; a3 += w.w * hv;
    }
    float* gp = acc + (kh * 16 + (rg << 2)) * 32 + lane;
    gp[0] = a0; gp[32] = a1; gp[64] = a2; gp[96] = a3;
}

__global__ void __launch_bounds__(256, 1)
k6_gru(const float* __restrict__ W_ih, const float* __restrict__ W_hh,
       const float* __restrict__ b_ih, const float* __restrict__ b_hh,
       const float* __restrict__ fc_w) {
    extern __shared__ float sm[];
    float* hs   = sm + SM_HS;
    float* wih  = sm + SM_WIH;
    float* whh  = sm + SM_WHH;
    float* xacc = sm + SM_XACC;
    float* gacc = sm + SM_GACC;
    float* hn   = sm + SM_HN;
    float* bih  = sm + SM_BIH;
    float* bhh  = sm + SM_BHH;
    float* fcw  = sm + SM_FCW;

    const int tid = threadIdx.x;
    const int bid = blockIdx.x;
    const int j0 = bid * 5;
    const int wid = tid >> 5;
    const int lane = tid & 31;
    const int rg = wid & 3;          // 4-row group within 16
    const int kh = wid >> 2;         // split-k half

    // stage weight rows transposed [k][16] (row 15 = zero dummy)
    for (int idx = tid; idx < HDIM * 16; idx += 256) {
        int k = idx >> 4, r = idx & 15;
        float vi = 0.f, vh = 0.f;
        if (r < 15) {
            int grow = (r / 5) * HDIM + j0 + (r % 5);
            vi = W_ih[(size_t)grow * HDIM + k];
            vh = W_hh[(size_t)grow * HDIM + k];
        }
        wih[idx] = vi;
        whh[idx] = vh;
    }
    if (tid < 15) {
        int grow = (tid / 5) * HDIM + j0 + (tid % 5);
        bih[tid] = b_ih[grow];
        bhh[tid] = b_hh[grow];
    }
    if (tid < 5) fcw[tid] = fc_w[j0 + tid];
    // zero own slice of h_0
    for (int i = tid; i < 5 * BATCH; i += 256)
        d_hbuf[0][(j0 + (i >> 5)) * BATCH + (i & 31)] = 0.f;
    grid_barrier();

    const int pc = tid >> 5;         // pointwise: local unit (0..4)
    const int pb = tid & 31;         // pointwise: batch
    const bool pw = (tid < 160);

    for (int t = 0; t < T_LEN; ++t) {
        // ---- phase 1: stage seq[t] and compute ih matvec -> xacc ----
        {
            const float4* src = (const float4*)(d_seq + (size_t)t * (HDIM * BATCH));
            float4* dst = (float4*)hs;
            for (int i = tid; i < (HDIM * BATCH) / 4; i += 256) dst[i] = src[i];
        }
        __syncthreads();
        matvec_16x32(hs, wih, xacc, kh, rg, lane);
        __syncthreads();
        // ---- phase 2: stage h (L2-coherent) and compute hh matvec ----
        {
            const float4* src = (const float4*)(d_hbuf[t & 1]);
            float4* dst = (float4*)hs;
            for (int i = tid; i < (HDIM * BATCH) / 4; i += 256) dst[i] = __ldcg(src + i);
        }
        __syncthreads();
        matvec_16x32(hs, whh, gacc, kh, rg, lane);
        __syncthreads();
        // ---- pointwise GRU cell: 5 units x 32 batch ----
        if (pw) {
            int rr = pc, rz = 5 + pc, rn = 10 + pc;
            float xpr = xacc[rr * 32 + pb] + xacc[(16 + rr) * 32 + pb] + bih[rr];
            float xpz = xacc[rz * 32 + pb] + xacc[(16 + rz) * 32 + pb] + bih[rz];
            float xpn = xacc[rn * 32 + pb] + xacc[(16 + rn) * 32 + pb] + bih[rn];
            float ghr = gacc[rr * 32 + pb] + gacc[(16 + rr) * 32 + pb] + bhh[rr];
            float ghz = gacc[rz * 32 + pb] + gacc[(16 + rz) * 32 + pb] + bhh[rz];
            float ghn = gacc[rn * 32 + pb] + gacc[(16 + rn) * 32 + pb] + bhh[rn];
            float r = 1.f / (1.f + expf(-(xpr + ghr)));
            float z = 1.f / (1.f + expf(-(xpz + ghz)));
            float n = tanhf(xpn + r * ghn);
            float hold = hs[(j0 + pc) * 32 + pb];
            float hnew = (1.f - z) * n + z * hold;
            __stcg(&d_hbuf[(t + 1) & 1][(j0 + pc) * BATCH + pb], hnew);
            hn[pc * 32 + pb] = hnew;
        }
        __syncthreads();
        if (tid < 32) {
            float fp = 0.f;
#pragma unroll
            for (int c = 0; c < 5; ++c) fp += hn[c * 32 + tid] * fcw[c];
            d_fcpart[((size_t)t * NB + bid) * 32 + tid] = fp;
        }
        grid_barrier();
    }
}

// ------------------- K7: fc reduction (deterministic) ----------------------
__global__ void k7_out(const float* __restrict__ fc_b, float* __restrict__ out) {
    int t = blockIdx.x;
    int b = threadIdx.x;   // 32 threads
    float s = fc_b[0];
    const float* p = d_fcpart + (size_t)t * NB * 32 + b;
#pragma unroll 16
    for (int i = 0; i < NB; ++i) s += p[i * 32];
    out[(size_t)b * T_LEN + t] = s;
}

// ------------------------- launch ------------------------------------------
extern "C" void kernel_launch(void* const* d_in, const int* in_sizes, int n_in,
                              void* d_out, int out_size) {
    const float* x        = (const float*)d_in[0];
    const float* a_vals   = (const float*)d_in[1];
    const float* w_vals   = (const float*)d_in[2];
    const float* dcls_w   = (const float*)d_in[3];
    const float* dcls_p   = (const float*)d_in[4];
    const float* dcls_b   = (const float*)d_in[5];
    const float* bn_gamma = (const float*)d_in[6];
    const float* bn_beta  = (const float*)d_in[7];
    const float* W_ih     = (const float*)d_in[8];
    const float* W_hh     = (const float*)d_in[9];
    const float* b_ih     = (const float*)d_in[10];
    const float* b_hh     = (const float*)d_in[11];
    const float* fc_w     = (const float*)d_in[12];
    const float* fc_b     = (const float*)d_in[13];
    float* out = (float*)d_out;

    cudaFuncSetAttribute(k3_dcls, cudaFuncAttributeMaxDynamicSharedMemorySize,
                         14 * 1012 * (int)sizeof(float));
    cudaFuncSetAttribute(k6_gru, cudaFuncAttributeMaxDynamicSharedMemorySize,
                         SM6_FLOATS * (int)sizeof(float));

    k1_highpass<<<dim3(BATCH, NF), 256>>>(x, a_vals, w_vals);
    k2_dk<<<(HDIM * 14 + 255) / 256, 256>>>(dcls_w, dcls_p);
    k3_dcls<<<dim3(10, BATCH), 256, 14 * 1012 * sizeof(float)>>>(dcls_b);
    k4_stats<<<64, 256>>>();
    k5_norm<<<HDIM, 256>>>(bn_gamma, bn_beta);
    k6_gru<<<NB, 256, SM6_FLOATS * sizeof(float)>>>(W_ih, W_hh, b_ih, b_hh, fc_w);
    k7_out<<<T_LEN, 32>>>(fc_b, out);
}

// round 7
// speedup vs baseline: 1.5316x; 1.5316x over previous
#include <cuda_runtime.h>
#include <math.h>
#include <stdint.h>

#define T_LEN 1000
#define BATCH 32
#define NF 34
#define HDIM 640
#define NB 128            // persistent blocks (5 hidden cols each)

// ------------------------- device scratch (~189 MB total) ------------------
__device__ float d_X2[BATCH * 2 * NF * T_LEN];           // 8.7 MB
__device__ float d_dkw0[HDIM * 14];
__device__ float d_dkw1[HDIM * 14];
__device__ int   d_dklo[HDIM * 14];
__device__ float d_Y[HDIM * BATCH * T_LEN];              // 81.9 MB  [hseq][b][t]
__device__ double d_p4sum[640];
__device__ double d_p4sq[640];
__device__ float d_mean[64];
__device__ float d_rstd[64];
__device__ float d_seq[(size_t)T_LEN * HDIM * BATCH];    // 81.9 MB  [t][k][b]
__device__ float d_hbuf[2][HDIM * BATCH];                // ping-pong h  [k][b]
__device__ float d_fcpart[(size_t)T_LEN * NB * BATCH];   // 16.4 MB

// ------------------------- grid barrier ------------------------------------
__device__ volatile unsigned g_epoch = 0;
__device__ unsigned g_count = 0;

__device__ __forceinline__ void grid_barrier() {
    __syncthreads();
    if (threadIdx.x == 0) {
        unsigned e = g_epoch;
        __threadfence();
        if (atomicAdd(&g_count, 1u) == NB - 1) {
            g_count = 0;
            __threadfence();
            g_epoch = e + 1;
        } else {
            while (g_epoch == e) { }
        }
        __threadfence();
    }
    __syncthreads();
}

// ------------------------- f32x2 helpers -----------------------------------
__device__ __forceinline__ unsigned long long ffma2(unsigned long long a,
                                                    unsigned long long b,
                                                    unsigned long long c) {
    unsigned long long d;
    asm("fma.rn.f32x2 %0, %1, %2, %3;" : "=l"(d) : "l"(a), "l"(b), "l"(c));
    return d;
}
__device__ __forceinline__ unsigned long long dup2(float w) {
    unsigned long long d;
    asm("mov.b64 %0, {%1, %1};" : "=l"(d) : "r"(__float_as_uint(w)));
    return d;
}

// ------------------- K1: truncated EMA highpass + rectify ------------------
__global__ void k1_highpass(const float* __restrict__ x,
                            const float* __restrict__ a_vals,
                            const float* __restrict__ w_vals) {
    int b = blockIdx.x, f = blockIdx.y;
    __shared__ float xs[T_LEN];
    __shared__ float cs[200];
    const float* xr = x + (size_t)(b * NF + f) * T_LEN;
    for (int i = threadIdx.x; i < T_LEN; i += 256) xs[i] = xr[i];
    float a = a_vals[f];
    float w = w_vals[f];
    float l2 = log2f(1.0f - a);
    for (int j = threadIdx.x; j < 200; j += 256) cs[j] = a * exp2f(l2 * (float)j);
    __syncthreads();
    for (int t = threadIdx.x; t < T_LEN; t += 256) {
        float low = 0.f;
        int jm = min(199, t);
        for (int j = 0; j <= jm; ++j) low += cs[j] * xs[t - j];
        float hp = xs[t] - w * low;
        d_X2[((size_t)(b * 2 + 0) * NF + f) * T_LEN + t] = fmaxf(hp, 0.f);
        d_X2[((size_t)(b * 2 + 1) * NF + f) * T_LEN + t] = fmaxf(-hp, 0.f);
    }
}

// ------------------- K2: DCLS triangular kernel -> 2 taps ------------------
__global__ void k2_dk(const float* __restrict__ dcls_w,
                      const float* __restrict__ dcls_p) {
    int idx = blockIdx.x * 256 + threadIdx.x;
    if (idx < HDIM * 14) {
        float p = fminf(fmaxf(dcls_p[idx], 0.f), 8.f);
        float lo = floorf(p);
        float fr = p - lo;
        float w = dcls_w[idx];
        d_dkw0[idx] = w * (1.f - fr);
        d_dkw1[idx] = w * fr;
        d_dklo[idx] = (int)lo;
    }
}

// ------------------- K3: DCLS grouped conv + bias --------------------------
__global__ void k3_dcls(const float* __restrict__ dcls_b) {
    int g = blockIdx.x;     // 0..9
    int b = blockIdx.y;     // 0..31
    extern __shared__ float us[];           // 14 * 1012 floats
    const int P = 1012;
    for (int i = threadIdx.x; i < 14 * P; i += 256) us[i] = 0.f;
    __syncthreads();
    for (int i = 0; i < 14; ++i) {
        int s = i / 7, kk = i % 7;
        const float* src = d_X2 + ((size_t)(b * 2 + s) * NF + g * 3 + kk) * T_LEN;
        for (int t = threadIdx.x; t < T_LEN; t += 256) us[i * P + 4 + t] = src[t];
    }
    __syncthreads();
    for (int c = 0; c < 64; ++c) {
        int h = g * 64 + c;                 // conv channel (group-major)
        float w0[14], w1[14]; int lo[14];
#pragma unroll
        for (int i = 0; i < 14; ++i) {
            w0[i] = d_dkw0[h * 14 + i];
            w1[i] = d_dkw1[h * 14 + i];
            lo[i] = d_dklo[h * 14 + i];
        }
        float bias = dcls_b[h];
        int hseq = c * 10 + g;              // seq feature index
        float* dst = d_Y + ((size_t)hseq * BATCH + b) * T_LEN;
        for (int t = threadIdx.x; t < T_LEN; t += 256) {
            float acc = bias;
#pragma unroll
            for (int i = 0; i < 14; ++i) {
                acc += w0[i] * us[i * P + t + lo[i]];
                acc += w1[i] * us[i * P + t + lo[i] + 1];
            }
            dst[t] = acc;
        }
    }
}

// ------------------- K4a: BN partial sums (640 blocks) ---------------------
__global__ void k4a_stats() {
    const int bid = blockIdx.x;             // 0..639, 32000 floats each
    const float4* p = (const float4*)(d_Y + (size_t)bid * 32000);
    double s = 0.0, s2 = 0.0;
    for (int i = threadIdx.x; i < 8000; i += 256) {
        float4 v = p[i];
        s  += (double)v.x + (double)v.y + (double)v.z + (double)v.w;
        s2 += (double)v.x * v.x + (double)v.y * v.y + (double)v.z * v.z + (double)v.w * v.w;
    }
    __shared__ double sh[256], sh2[256];
    sh[threadIdx.x] = s; sh2[threadIdx.x] = s2;
    __syncthreads();
    for (int o = 128; o > 0; o >>= 1) {
        if (threadIdx.x < o) { sh[threadIdx.x] += sh[threadIdx.x + o]; sh2[threadIdx.x] += sh2[threadIdx.x + o]; }
        __syncthreads();
    }
    if (threadIdx.x == 0) { d_p4sum[bid] = sh[0]; d_p4sq[bid] = sh2[0]; }
}

// ------------------- K4b: combine -> mean/rstd -----------------------------
__global__ void k4b_stats() {
    int c = threadIdx.x;                    // 64 threads
    double s = 0.0, s2 = 0.0;
#pragma unroll
    for (int j = 0; j < 10; ++j) { s += d_p4sum[c * 10 + j]; s2 += d_p4sq[c * 10 + j]; }
    double mean = s / 320000.0;
    double var = s2 / 320000.0 - mean * mean;
    d_mean[c] = (float)mean;
    d_rstd[c] = (float)(1.0 / sqrt(var + 1e-5));
}

// ------------------- K5: normalize + sigmoid -> seq[t][k][b] ---------------
// smem-transposed tiles so both the read (t-fast) and the write (b-fast) coalesce
__global__ void k5_norm(const float* __restrict__ gamma,
                        const float* __restrict__ beta) {
    int h = blockIdx.x;                // 0..639 (= c*10 + g)
    int c = h / 10;
    float m = d_mean[c], r = d_rstd[c], ga = gamma[c], be = beta[c];
    const float* src = d_Y + (size_t)h * BATCH * T_LEN;
    __shared__ float ts[32][257];
    for (int t0 = 0; t0 < T_LEN; t0 += 256) {
        __syncthreads();
        for (int i = threadIdx.x; i < 32 * 256; i += 256) {
            int b = i >> 8, tl = i & 255;
            if (t0 + tl < T_LEN) ts[b][tl] = src[(size_t)b * T_LEN + t0 + tl];
        }
        __syncthreads();
        int b2 = threadIdx.x & 31, tl2 = threadIdx.x >> 5;
        for (int tt = tl2; tt < 256 && t0 + tt < T_LEN; tt += 8) {
            float v = (ts[b2][tt] - m) * r * ga + be;
            float sg = 1.f / (1.f + expf(-v));
            d_seq[(size_t)(t0 + tt) * (HDIM * BATCH) + h * BATCH + b2] = sg;
        }
    }
}

// ------------------- K6: persistent fused GRU (f32x2 matvecs) --------------
// SMEM (floats): hs[640*32] | wih[640*16] | whh[640*16] | xacc[4*16*32]
//                gacc[4*16*32] | hn[5*32] | bih[16] | bhh[16] | fcw[8]
#define SM_HS   0
#define SM_WIH  (SM_HS + HDIM * BATCH)          // 20480
#define SM_WHH  (SM_WIH + HDIM * 16)            // +10240
#define SM_XACC (SM_WHH + HDIM * 16)            // +10240
#define SM_GACC (SM_XACC + 4 * 16 * 32)         // +2048
#define SM_HN   (SM_GACC + 4 * 16 * 32)         // +2048
#define SM_BIH  (SM_HN + 5 * 32)
#define SM_BHH  (SM_BIH + 16)
#define SM_FCW  (SM_BHH + 16)
#define SM6_FLOATS (SM_FCW + 8)                 // 45384 floats = 181,536 B

// thread mapping (per matvec): warp w: rg2=w&1 -> rows r0=rg2*8..+8; kh=w>>1 (0..3)
// lane l: bq=l&7 -> batches 4bq..4bq+3; kq=l>>3 (0..3); ks=kh*4+kq; k in [ks*40,+40)
__device__ __forceinline__ void matvec_f32x2(const float* __restrict__ vec,
                                             const float* __restrict__ wmat,
                                             float* __restrict__ accbuf,
                                             int rg2, int kh, int bq, int kq,
                                             int lane) {
    const int r0 = rg2 * 8;
    const int k0 = (kh * 4 + kq) * 40;
    unsigned long long acc[8][2];
#pragma unroll
    for (int r = 0; r < 8; ++r) { acc[r][0] = 0ull; acc[r][1] = 0ull; }
    const float* hp = vec + (size_t)k0 * 32 + 4 * bq;
    const float* wp = wmat + (size_t)k0 * 16 + r0;
#pragma unroll 4
    for (int kk = 0; kk < 40; ++kk) {
        const ulonglong2 hv = *(const ulonglong2*)(hp + kk * 32);
        const float4 wA = *(const float4*)(wp + kk * 16);
        const float4 wB = *(const float4*)(wp + kk * 16 + 4);
        unsigned long long wd;
        wd = dup2(wA.x); acc[0][0] = ffma2(hv.x, wd, acc[0][0]); acc[0][1] = ffma2(hv.y, wd, acc[0][1]);
        wd = dup2(wA.y); acc[1][0] = ffma2(hv.x, wd, acc[1][0]); acc[1][1] = ffma2(hv.y, wd, acc[1][1]);
        wd = dup2(wA.z); acc[2][0] = ffma2(hv.x, wd, acc[2][0]); acc[2][1] = ffma2(hv.y, wd, acc[2][1]);
        wd = dup2(wA.w); acc[3][0] = ffma2(hv.x, wd, acc[3][0]); acc[3][1] = ffma2(hv.y, wd, acc[3][1]);
        wd = dup2(wB.x); acc[4][0] = ffma2(hv.x, wd, acc[4][0]); acc[4][1] = ffma2(hv.y, wd, acc[4][1]);
        wd = dup2(wB.y); acc[5][0] = ffma2(hv.x, wd, acc[5][0]); acc[5][1] = ffma2(hv.y, wd, acc[5][1]);
        wd = dup2(wB.z); acc[6][0] = ffma2(hv.x, wd, acc[6][0]); acc[6][1] = ffma2(hv.y, wd, acc[6][1]);
        wd = dup2(wB.w); acc[7][0] = ffma2(hv.x, wd, acc[7][0]); acc[7][1] = ffma2(hv.y, wd, acc[7][1]);
    }
    // reduce over kq (lanes l, l^8, l^16, l^24)
#pragma unroll
    for (int r = 0; r < 8; ++r) {
#pragma unroll
        for (int p = 0; p < 2; ++p) {
            unsigned long long v = acc[r][p];
            float2 f = *(float2*)&v;
            f.x += __shfl_xor_sync(0xffffffffu, f.x, 8);
            f.y += __shfl_xor_sync(0xffffffffu, f.y, 8);
            f.x += __shfl_xor_sync(0xffffffffu, f.x, 16);
            f.y += __shfl_xor_sync(0xffffffffu, f.y, 16);
            *(float2*)&acc[r][p] = f;
        }
    }
    if (lane < 8) {
#pragma unroll
        for (int r = 0; r < 8; ++r) {
            float2 a0 = *(float2*)&acc[r][0];
            float2 a1 = *(float2*)&acc[r][1];
            float4 o; o.x = a0.x; o.y = a0.y; o.z = a1.x; o.w = a1.y;
            *(float4*)&accbuf[(kh * 16 + r0 + r) * 32 + 4 * bq] = o;
        }
    }
}

__global__ void __launch_bounds__(256, 1)
k6_gru(const float* __restrict__ W_ih, const float* __restrict__ W_hh,
       const float* __restrict__ b_ih, const float* __restrict__ b_hh,
       const float* __restrict__ fc_w) {
    extern __shared__ float sm[];
    float* hs   = sm + SM_HS;
    float* wih  = sm + SM_WIH;
    float* whh  = sm + SM_WHH;
    float* xacc = sm + SM_XACC;
    float* gacc = sm + SM_GACC;
    float* hn   = sm + SM_HN;
    float* bih  = sm + SM_BIH;
    float* bhh  = sm + SM_BHH;
    float* fcw  = sm + SM_FCW;

    const int tid = threadIdx.x;
    const int bid = blockIdx.x;
    const int j0 = bid * 5;
    const int wid = tid >> 5;
    const int lane = tid & 31;
    const int rg2 = wid & 1;
    const int kh = wid >> 1;
    const int bq = lane & 7;
    const int kq = lane >> 3;

    // stage weight rows transposed [k][16] (row 15 = zero dummy)
    for (int idx = tid; idx < HDIM * 16; idx += 256) {
        int k = idx >> 4, r = idx & 15;
        float vi = 0.f, vh = 0.f;
        if (r < 15) {
            int grow = (r / 5) * HDIM + j0 + (r % 5);
            vi = W_ih[(size_t)grow * HDIM + k];
            vh = W_hh[(size_t)grow * HDIM + k];
        }
        wih[idx] = vi;
        whh[idx] = vh;
    }
    if (tid < 15) {
        int grow = (tid / 5) * HDIM + j0 + (tid % 5);
        bih[tid] = b_ih[grow];
        bhh[tid] = b_hh[grow];
    }
    if (tid < 5) fcw[tid] = fc_w[j0 + tid];
    for (int i = tid; i < 5 * BATCH; i += 256)
        d_hbuf[0][(j0 + (i >> 5)) * BATCH + (i & 31)] = 0.f;
    grid_barrier();

    const int pc = tid >> 5;         // pointwise: local unit (0..4)
    const int pb = tid & 31;         // pointwise: batch
    const bool pw = (tid < 160);

    for (int t = 0; t < T_LEN; ++t) {
        // ---- phase 1: stage seq[t]; ih matvec -> xacc ----
        {
            const float4* src = (const float4*)(d_seq + (size_t)t * (HDIM * BATCH));
            float4* dst = (float4*)hs;
#pragma unroll
            for (int i = 0; i < 20; ++i) dst[tid + 256 * i] = src[tid + 256 * i];
        }
        __syncthreads();
        matvec_f32x2(hs, wih, xacc, rg2, kh, bq, kq, lane);
        __syncthreads();
        // ---- phase 2: stage h (L2-coherent); hh matvec -> gacc ----
        {
            const float4* src = (const float4*)(d_hbuf[t & 1]);
            float4* dst = (float4*)hs;
#pragma unroll
            for (int i = 0; i < 20; ++i) dst[tid + 256 * i] = __ldcg(src + tid + 256 * i);
        }
        __syncthreads();
        matvec_f32x2(hs, whh, gacc, rg2, kh, bq, kq, lane);
        __syncthreads();
        // ---- pointwise GRU cell: 5 units x 32 batch ----
        if (pw) {
            int rr = pc, rz = 5 + pc, rn = 10 + pc;
            float xpr = xacc[rr*32+pb] + xacc[512+rr*32+pb] + xacc[1024+rr*32+pb] + xacc[1536+rr*32+pb] + bih[rr];
            float xpz = xacc[rz*32+pb] + xacc[512+rz*32+pb] + xacc[1024+rz*32+pb] + xacc[1536+rz*32+pb] + bih[rz];
            float xpn = xacc[rn*32+pb] + xacc[512+rn*32+pb] + xacc[1024+rn*32+pb] + xacc[1536+rn*32+pb] + bih[rn];
            float ghr = gacc[rr*32+pb] + gacc[512+rr*32+pb] + gacc[1024+rr*32+pb] + gacc[1536+rr*32+pb] + bhh[rr];
            float ghz = gacc[rz*32+pb] + gacc[512+rz*32+pb] + gacc[1024+rz*32+pb] + gacc[1536+rz*32+pb] + bhh[rz];
            float ghn = gacc[rn*32+pb] + gacc[512+rn*32+pb] + gacc[1024+rn*32+pb] + gacc[1536+rn*32+pb] + bhh[rn];
            float r = 1.f / (1.f + expf(-(xpr + ghr)));
            float z = 1.f / (1.f + expf(-(xpz + ghz)));
            float n = tanhf(xpn + r * ghn);
            float hold = hs[(j0 + pc) * 32 + pb];
            float hnew = (1.f - z) * n + z * hold;
            __stcg(&d_hbuf[(t + 1) & 1][(j0 + pc) * BATCH + pb], hnew);
            hn[pc * 32 + pb] = hnew;
        }
        __syncthreads();
        if (tid < 32) {
            float fp = 0.f;
#pragma unroll
            for (int c = 0; c < 5; ++c) fp += hn[c * 32 + tid] * fcw[c];
            d_fcpart[((size_t)t * NB + bid) * 32 + tid] = fp;
        }
        grid_barrier();
    }
}

// ------------------- K7: fc reduction (deterministic) ----------------------
__global__ void k7_out(const float* __restrict__ fc_b, float* __restrict__ out) {
    int t = blockIdx.x;
    int b = threadIdx.x;   // 32 threads
    float s = fc_b[0];
    const float* p = d_fcpart + (size_t)t * NB * 32 + b;
#pragma unroll 16
    for (int i = 0; i < NB; ++i) s += p[i * 32];
    out[(size_t)b * T_LEN + t] = s;
}

// ------------------------- launch ------------------------------------------
extern "C" void kernel_launch(void* const* d_in, const int* in_sizes, int n_in,
                              void* d_out, int out_size) {
    const float* x        = (const float*)d_in[0];
    const float* a_vals   = (const float*)d_in[1];
    const float* w_vals   = (const float*)d_in[2];
    const float* dcls_w   = (const float*)d_in[3];
    const float* dcls_p   = (const float*)d_in[4];
    const float* dcls_b   = (const float*)d_in[5];
    const float* bn_gamma = (const float*)d_in[6];
    const float* bn_beta  = (const float*)d_in[7];
    const float* W_ih     = (const float*)d_in[8];
    const float* W_hh     = (const float*)d_in[9];
    const float* b_ih     = (const float*)d_in[10];
    const float* b_hh     = (const float*)d_in[11];
    const float* fc_w     = (const float*)d_in[12];
    const float* fc_b     = (const float*)d_in[13];
    float* out = (float*)d_out;

    cudaFuncSetAttribute(k3_dcls, cudaFuncAttributeMaxDynamicSharedMemorySize,
                         14 * 1012 * (int)sizeof(float));
    cudaFuncSetAttribute(k6_gru, cudaFuncAttributeMaxDynamicSharedMemorySize,
                         SM6_FLOATS * (int)sizeof(float));

    k1_highpass<<<dim3(BATCH, NF), 256>>>(x, a_vals, w_vals);
    k2_dk<<<(HDIM * 14 + 255) / 256, 256>>>(dcls_w, dcls_p);
    k3_dcls<<<dim3(10, BATCH), 256, 14 * 1012 * sizeof(float)>>>(dcls_b);
    k4a_stats<<<640, 256>>>();
    k4b_stats<<<1, 64>>>();
    k5_norm<<<HDIM, 256>>>(bn_gamma, bn_beta);
    k6_gru<<<NB, 256, SM6_FLOATS * sizeof(float)>>>(W_ih, W_hh, b_ih, b_hh, fc_w);
    k7_out<<<T_LEN, 32>>>(fc_b, out);
}

// round 10
// speedup vs baseline: 2.0314x; 1.3263x over previous
#include <cuda_runtime.h>
#include <math.h>
#include <stdint.h>

#define T_LEN 1000
#define BATCH 32
#define NF 34
#define HDIM 640
#define NB 128            // persistent blocks (5 hidden cols each)

// ------------------------- device scratch ----------------------------------
__device__ float d_X2[BATCH * 2 * NF * T_LEN];           // 8.7 MB
__device__ float d_dkw0[HDIM * 14];
__device__ float d_dkw1[HDIM * 14];
__device__ int   d_dklo[HDIM * 14];
__device__ float d_Y[HDIM * BATCH * T_LEN];              // 81.9 MB  [hseq][b][t]
__device__ double d_p4sum[640];
__device__ double d_p4sq[640];
__device__ float d_mean[64];
__device__ float d_rstd[64];
__device__ float d_seq[(size_t)T_LEN * HDIM * BATCH];    // 81.9 MB  [t][k][b]
__device__ float d_hbuf[2][HDIM * BATCH];                // ping-pong h  [k][b]
__device__ float d_fcpart[(size_t)T_LEN * NB * BATCH];   // 16.4 MB

// ------------------------- grid barrier ------------------------------------
__device__ volatile unsigned g_epoch = 0;
__device__ unsigned g_count = 0;

__device__ __forceinline__ void grid_barrier() {
    __syncthreads();
    if (threadIdx.x == 0) {
        unsigned e = g_epoch;
        __threadfence();
        if (atomicAdd(&g_count, 1u) == NB - 1) {
            g_count = 0;
            __threadfence();
            g_epoch = e + 1;
        } else {
            while (g_epoch == e) { }
        }
        __threadfence();
    }
    __syncthreads();
}

// split arrive/wait: ih matvec runs between them to hide barrier latency
__device__ __forceinline__ unsigned barrier_arrive() {
    unsigned e = 0;
    __syncthreads();
    if (threadIdx.x == 0) {
        e = g_epoch;
        __threadfence();
        if (atomicAdd(&g_count, 1u) == NB - 1) {
            g_count = 0;
            __threadfence();
            g_epoch = e + 1;
        }
    }
    return e;
}
__device__ __forceinline__ void barrier_wait(unsigned e) {
    if (threadIdx.x == 0) {
        while (g_epoch == e) { }
        __threadfence();
    }
    __syncthreads();
}

// ------------------------- f32x2 / cp.async helpers ------------------------
__device__ __forceinline__ unsigned long long ffma2(unsigned long long a,
                                                    unsigned long long b,
                                                    unsigned long long c) {
    unsigned long long d;
    asm("fma.rn.f32x2 %0, %1, %2, %3;" : "=l"(d) : "l"(a), "l"(b), "l"(c));
    return d;
}
__device__ __forceinline__ unsigned long long dup2(float w) {
    unsigned long long d;
    asm("mov.b64 %0, {%1, %1};" : "=l"(d) : "r"(__float_as_uint(w)));
    return d;
}
__device__ __forceinline__ void cp16(uint32_t dst, const void* src) {
    asm volatile("cp.async.cg.shared.global [%0], [%1], 16;" :: "r"(dst), "l"(src));
}
#define CP_COMMIT() asm volatile("cp.async.commit_group;")
#define CP_WAIT(N)  asm volatile("cp.async.wait_group %0;" :: "n"(N))

// ------------------- K1: truncated EMA highpass + rectify ------------------
__global__ void k1_highpass(const float* __restrict__ x,
                            const float* __restrict__ a_vals,
                            const float* __restrict__ w_vals) {
    int b = blockIdx.x, f = blockIdx.y;
    __shared__ float xs[T_LEN];
    __shared__ float cs[200];
    const float* xr = x + (size_t)(b * NF + f) * T_LEN;
    for (int i = threadIdx.x; i < T_LEN; i += 256) xs[i] = xr[i];
    float a = a_vals[f];
    float w = w_vals[f];
    float l2 = log2f(1.0f - a);
    for (int j = threadIdx.x; j < 200; j += 256) cs[j] = a * exp2f(l2 * (float)j);
    __syncthreads();
    for (int t = threadIdx.x; t < T_LEN; t += 256) {
        float low = 0.f;
        int jm = min(199, t);
        for (int j = 0; j <= jm; ++j) low += cs[j] * xs[t - j];
        float hp = xs[t] - w * low;
        d_X2[((size_t)(b * 2 + 0) * NF + f) * T_LEN + t] = fmaxf(hp, 0.f);
        d_X2[((size_t)(b * 2 + 1) * NF + f) * T_LEN + t] = fmaxf(-hp, 0.f);
    }
}

// ------------------- K2: DCLS triangular kernel -> 2 taps ------------------
__global__ void k2_dk(const float* __restrict__ dcls_w,
                      const float* __restrict__ dcls_p) {
    int idx = blockIdx.x * 256 + threadIdx.x;
    if (idx < HDIM * 14) {
        float p = fminf(fmaxf(dcls_p[idx], 0.f), 8.f);
        float lo = floorf(p);
        float fr = p - lo;
        float w = dcls_w[idx];
        d_dkw0[idx] = w * (1.f - fr);
        d_dkw1[idx] = w * fr;
        d_dklo[idx] = (int)lo;
    }
}

// ------------------- K3: DCLS grouped conv + bias --------------------------
__global__ void k3_dcls(const float* __restrict__ dcls_b) {
    int g = blockIdx.x;     // 0..9
    int b = blockIdx.y;     // 0..31
    extern __shared__ float us[];           // 14 * 1012 floats
    const int P = 1012;
    for (int i = threadIdx.x; i < 14 * P; i += 256) us[i] = 0.f;
    __syncthreads();
    for (int i = 0; i < 14; ++i) {
        int s = i / 7, kk = i % 7;
        const float* src = d_X2 + ((size_t)(b * 2 + s) * NF + g * 3 + kk) * T_LEN;
        for (int t = threadIdx.x; t < T_LEN; t += 256) us[i * P + 4 + t] = src[t];
    }
    __syncthreads();
    for (int c = 0; c < 64; ++c) {
        int h = g * 64 + c;
        float w0[14], w1[14]; int lo[14];
#pragma unroll
        for (int i = 0; i < 14; ++i) {
            w0[i] = d_dkw0[h * 14 + i];
            w1[i] = d_dkw1[h * 14 + i];
            lo[i] = d_dklo[h * 14 + i];
        }
        float bias = dcls_b[h];
        int hseq = c * 10 + g;
        float* dst = d_Y + ((size_t)hseq * BATCH + b) * T_LEN;
        for (int t = threadIdx.x; t < T_LEN; t += 256) {
            float acc = bias;
#pragma unroll
            for (int i = 0; i < 14; ++i) {
                acc += w0[i] * us[i * P + t + lo[i]];
                acc += w1[i] * us[i * P + t + lo[i] + 1];
            }
            dst[t] = acc;
        }
    }
}

// ------------------- K4a: BN partial sums (640 blocks, 256 thr) ------------
__global__ void k4a_stats() {
    const int bid = blockIdx.x;
    const float4* p = (const float4*)(d_Y + (size_t)bid * 32000);
    double s0 = 0.0, s1 = 0.0, q0 = 0.0, q1 = 0.0;
    for (int i = threadIdx.x; i < 8000; i += 512) {
        float4 v = p[i];
        s0 += (double)v.x + (double)v.y;
        s1 += (double)v.z + (double)v.w;
        q0 += (double)v.x * v.x + (double)v.y * v.y;
        q1 += (double)v.z * v.z + (double)v.w * v.w;
        int i2 = i + 256;
        if (i2 < 8000) {
            float4 u = p[i2];
            s0 += (double)u.x + (double)u.y;
            s1 += (double)u.z + (double)u.w;
            q0 += (double)u.x * u.x + (double)u.y * u.y;
            q1 += (double)u.z * u.z + (double)u.w * u.w;
        }
    }
    double s = s0 + s1, s2 = q0 + q1;
    __shared__ double sh[256], sh2[256];
    sh[threadIdx.x] = s; sh2[threadIdx.x] = s2;
    __syncthreads();
    for (int o = 128; o > 0; o >>= 1) {
        if (threadIdx.x < o) { sh[threadIdx.x] += sh[threadIdx.x + o]; sh2[threadIdx.x] += sh2[threadIdx.x + o]; }
        __syncthreads();
    }
    if (threadIdx.x == 0) { d_p4sum[bid] = sh[0]; d_p4sq[bid] = sh2[0]; }
}

// ------------------- K4b: combine -> mean/rstd -----------------------------
__global__ void k4b_stats() {
    int c = threadIdx.x;                    // 64 threads
    double s = 0.0, s2 = 0.0;
#pragma unroll
    for (int j = 0; j < 10; ++j) { s += d_p4sum[c * 10 + j]; s2 += d_p4sq[c * 10 + j]; }
    double mean = s / 320000.0;
    double var = s2 / 320000.0 - mean * mean;
    d_mean[c] = (float)mean;
    d_rstd[c] = (float)(1.0 / sqrt(var + 1e-5));
}

// ------------------- K5: normalize + sigmoid -> seq[t][k][b] ---------------
__global__ void k5_norm(const float* __restrict__ gamma,
                        const float* __restrict__ beta) {
    int h = blockIdx.x;
    int c = h / 10;
    float m = d_mean[c], r = d_rstd[c], ga = gamma[c], be = beta[c];
    const float* src = d_Y + (size_t)h * BATCH * T_LEN;
    __shared__ float ts[32][257];
    for (int t0 = 0; t0 < T_LEN; t0 += 256) {
        __syncthreads();
        for (int i = threadIdx.x; i < 32 * 256; i += 256) {
            int b = i >> 8, tl = i & 255;
            if (t0 + tl < T_LEN) ts[b][tl] = src[(size_t)b * T_LEN + t0 + tl];
        }
        __syncthreads();
        int b2 = threadIdx.x & 31, tl2 = threadIdx.x >> 5;
        for (int tt = tl2; tt < 256 && t0 + tt < T_LEN; tt += 8) {
            float v = (ts[b2][tt] - m) * r * ga + be;
            float sg = 1.f / (1.f + expf(-v));
            d_seq[(size_t)(t0 + tt) * (HDIM * BATCH) + h * BATCH + b2] = sg;
        }
    }
}

// ------------------- K6: persistent GRU, pipelined staging -----------------
// SMEM (floats): sbuf[640*32] | hb[2][160*32] | wih[640*16] | whh[640*16]
//                xacc[4*16*32] | gacc[4*16*32] | hn[5*32] | bih[16] | bhh[16] | fcw[8]
#define SM_SBUF 0
#define SM_HB   (SM_SBUF + HDIM * BATCH)        // 20480
#define SM_WIH  (SM_HB + 2 * 160 * 32)          // +10240
#define SM_WHH  (SM_WIH + HDIM * 16)            // +10240
#define SM_XACC (SM_WHH + HDIM * 16)            // +10240
#define SM_GACC (SM_XACC + 4 * 16 * 32)         // +2048
#define SM_HN   (SM_GACC + 4 * 16 * 32)         // +2048
#define SM_BIH  (SM_HN + 5 * 32)
#define SM_BHH  (SM_BIH + 16)
#define SM_FCW  (SM_BHH + 16)
#define SM6_FLOATS (SM_FCW + 8)                 // 55496 floats = 221,984 B

// ih matvec: warp w (rg2=w&1 -> rows r0=8*rg2; kh=w>>1); lane (bq=l&7, kq=l>>3)
__device__ __forceinline__ void matvec_ih(const float* __restrict__ vec,
                                          const float* __restrict__ wmat,
                                          float* __restrict__ accbuf,
                                          int rg2, int kh, int bq, int kq,
                                          int lane) {
    const int r0 = rg2 * 8;
    const int k0 = (kh * 4 + kq) * 40;
    unsigned long long acc[8][2];
#pragma unroll
    for (int r = 0; r < 8; ++r) { acc[r][0] = 0ull; acc[r][1] = 0ull; }
    const float* hp = vec + (size_t)k0 * 32 + 4 * bq;
    const float* wp = wmat + (size_t)k0 * 16 + r0;
#pragma unroll 4
    for (int kk = 0; kk < 40; ++kk) {
        const ulonglong2 hv = *(const ulonglong2*)(hp + kk * 32);
        const float4 wA = *(const float4*)(wp + kk * 16);
        const float4 wB = *(const float4*)(wp + kk * 16 + 4);
        unsigned long long wd;
        wd = dup2(wA.x); acc[0][0] = ffma2(hv.x, wd, acc[0][0]); acc[0][1] = ffma2(hv.y, wd, acc[0][1]);
        wd = dup2(wA.y); acc[1][0] = ffma2(hv.x, wd, acc[1][0]); acc[1][1] = ffma2(hv.y, wd, acc[1][1]);
        wd = dup2(wA.z); acc[2][0] = ffma2(hv.x, wd, acc[2][0]); acc[2][1] = ffma2(hv.y, wd, acc[2][1]);
        wd = dup2(wA.w); acc[3][0] = ffma2(hv.x, wd, acc[3][0]); acc[3][1] = ffma2(hv.y, wd, acc[3][1]);
        wd = dup2(wB.x); acc[4][0] = ffma2(hv.x, wd, acc[4][0]); acc[4][1] = ffma2(hv.y, wd, acc[4][1]);
        wd = dup2(wB.y); acc[5][0] = ffma2(hv.x, wd, acc[5][0]); acc[5][1] = ffma2(hv.y, wd, acc[5][1]);
        wd = dup2(wB.z); acc[6][0] = ffma2(hv.x, wd, acc[6][0]); acc[6][1] = ffma2(hv.y, wd, acc[6][1]);
        wd = dup2(wB.w); acc[7][0] = ffma2(hv.x, wd, acc[7][0]); acc[7][1] = ffma2(hv.y, wd, acc[7][1]);
    }
#pragma unroll
    for (int r = 0; r < 8; ++r) {
#pragma unroll
        for (int p = 0; p < 2; ++p) {
            unsigned long long v = acc[r][p];
            float2 f = *(float2*)&v;
            f.x += __shfl_xor_sync(0xffffffffu, f.x, 8);
            f.y += __shfl_xor_sync(0xffffffffu, f.y, 8);
            f.x += __shfl_xor_sync(0xffffffffu, f.x, 16);
            f.y += __shfl_xor_sync(0xffffffffu, f.y, 16);
            *(float2*)&acc[r][p] = f;
        }
    }
    if (lane < 8) {
#pragma unroll
        for (int r = 0; r < 8; ++r) {
            float2 a0 = *(float2*)&acc[r][0];
            float2 a1 = *(float2*)&acc[r][1];
            float4 o; o.x = a0.x; o.y = a0.y; o.z = a1.x; o.w = a1.y;
            *(float4*)&accbuf[(kh * 16 + r0 + r) * 32 + 4 * bq] = o;
        }
    }
}

// hh chunk: 10 k per thread, accumulate into persistent acc
__device__ __forceinline__ void hh_chunk(const float* __restrict__ hb_,
                                         const float* __restrict__ wchunk,
                                         unsigned long long acc[8][2],
                                         int koff, int r0, int bq) {
    const float* hp = hb_ + (size_t)koff * 32 + 4 * bq;
    const float* wp = wchunk + (size_t)koff * 16 + r0;
#pragma unroll
    for (int kk = 0; kk < 10; ++kk) {
        const ulonglong2 hv = *(const ulonglong2*)(hp + kk * 32);
        const float4 wA = *(const float4*)(wp + kk * 16);
        const float4 wB = *(const float4*)(wp + kk * 16 + 4);
        unsigned long long wd;
        wd = dup2(wA.x); acc[0][0] = ffma2(hv.x, wd, acc[0][0]); acc[0][1] = ffma2(hv.y, wd, acc[0][1]);
        wd = dup2(wA.y); acc[1][0] = ffma2(hv.x, wd, acc[1][0]); acc[1][1] = ffma2(hv.y, wd, acc[1][1]);
        wd = dup2(wA.z); acc[2][0] = ffma2(hv.x, wd, acc[2][0]); acc[2][1] = ffma2(hv.y, wd, acc[2][1]);
        wd = dup2(wA.w); acc[3][0] = ffma2(hv.x, wd, acc[3][0]); acc[3][1] = ffma2(hv.y, wd, acc[3][1]);
        wd = dup2(wB.x); acc[4][0] = ffma2(hv.x, wd, acc[4][0]); acc[4][1] = ffma2(hv.y, wd, acc[4][1]);
        wd = dup2(wB.y); acc[5][0] = ffma2(hv.x, wd, acc[5][0]); acc[5][1] = ffma2(hv.y, wd, acc[5][1]);
        wd = dup2(wB.z); acc[6][0] = ffma2(hv.x, wd, acc[6][0]); acc[6][1] = ffma2(hv.y, wd, acc[6][1]);
        wd = dup2(wB.w); acc[7][0] = ffma2(hv.x, wd, acc[7][0]); acc[7][1] = ffma2(hv.y, wd, acc[7][1]);
    }
}

__global__ void __launch_bounds__(256, 1)
k6_gru(const float* __restrict__ W_ih, const float* __restrict__ W_hh,
       const float* __restrict__ b_ih, const float* __restrict__ b_hh,
       const float* __restrict__ fc_w) {
    extern __shared__ float sm[];
    float* sbuf = sm + SM_SBUF;
    float* hb0  = sm + SM_HB;
    float* hb1  = sm + SM_HB + 160 * 32;
    float* wih  = sm + SM_WIH;
    float* whh  = sm + SM_WHH;
    float* xacc = sm + SM_XACC;
    float* gacc = sm + SM_GACC;
    float* hn   = sm + SM_HN;
    float* bih  = sm + SM_BIH;
    float* bhh  = sm + SM_BHH;
    float* fcw  = sm + SM_FCW;

    const int tid = threadIdx.x;
    const int bid = blockIdx.x;
    const int j0 = bid * 5;
    const int wid = tid >> 5;
    const int lane = tid & 31;
    const int rg2 = wid & 1;
    const int kh = wid >> 1;
    const int bq = lane & 7;
    const int kq = lane >> 3;
    const int r0 = rg2 * 8;
    const int koff = (kh * 4 + kq) * 10;     // k offset within a 160-k chunk

    uint32_t sbuf_a = (uint32_t)__cvta_generic_to_shared(sbuf);
    uint32_t hb_a[2] = { (uint32_t)__cvta_generic_to_shared(hb0),
                         (uint32_t)__cvta_generic_to_shared(hb1) };

    // stage weight rows transposed [k][16] (row 15 = zero dummy)
    for (int idx = tid; idx < HDIM * 16; idx += 256) {
        int k = idx >> 4, r = idx & 15;
        float vi = 0.f, vh = 0.f;
        if (r < 15) {
            int grow = (r / 5) * HDIM + j0 + (r % 5);
            vi = W_ih[(size_t)grow * HDIM + k];
            vh = W_hh[(size_t)grow * HDIM + k];
        }
        wih[idx] = vi;
        whh[idx] = vh;
    }
    if (tid < 15) {
        int grow = (tid / 5) * HDIM + j0 + (tid % 5);
        bih[tid] = b_ih[grow];
        bhh[tid] = b_hh[grow];
    }
    if (tid < 5) fcw[tid] = fc_w[j0 + tid];
    for (int i = tid; i < 5 * BATCH; i += 256)
        d_hbuf[0][(j0 + (i >> 5)) * BATCH + (i & 31)] = 0.f;

    // prefetch seq[0] into sbuf (block-local, no barrier needed)
    {
        const float4* src = (const float4*)d_seq;
#pragma unroll
        for (int i = 0; i < 20; ++i)
            cp16(sbuf_a + (tid + 256 * i) * 16, src + tid + 256 * i);
        CP_COMMIT();
    }
    grid_barrier();

    const int pc = tid >> 5;
    const int pb = tid & 31;
    const bool pw = (tid < 160);

    for (int t = 0; t < T_LEN; ++t) {
        CP_WAIT(0);
        __syncthreads();                       // sbuf = seq[t] ready; prev step state retired
        unsigned ep = barrier_arrive();        // release our h[t] contribution (written last iter)
        matvec_ih(sbuf, wih, xacc, rg2, kh, bq, kq, lane);   // h-independent; hides barrier
        barrier_wait(ep);                      // h[t] globally ready

        float hold = 0.f;
        if (pw) hold = __ldcg(&d_hbuf[t & 1][(j0 + pc) * BATCH + pb]);

        const float* hsrc = d_hbuf[t & 1];
        // pipeline h chunks (4 x 160 k), double-buffered
        {
            const float4* s0 = (const float4*)(hsrc);
#pragma unroll
            for (int i = 0; i < 5; ++i) cp16(hb_a[0] + (tid + 256 * i) * 16, s0 + tid + 256 * i);
            CP_COMMIT();
            const float4* s1 = (const float4*)(hsrc + 160 * 32);
#pragma unroll
            for (int i = 0; i < 5; ++i) cp16(hb_a[1] + (tid + 256 * i) * 16, s1 + tid + 256 * i);
            CP_COMMIT();
        }
        unsigned long long acc[8][2];
#pragma unroll
        for (int r = 0; r < 8; ++r) { acc[r][0] = 0ull; acc[r][1] = 0ull; }

        CP_WAIT(1); __syncthreads();
        hh_chunk(hb0, whh + 0 * 160 * 16, acc, koff, r0, bq);
        __syncthreads();
        {
            const float4* s2 = (const float4*)(hsrc + 2 * 160 * 32);
#pragma unroll
            for (int i = 0; i < 5; ++i) cp16(hb_a[0] + (tid + 256 * i) * 16, s2 + tid + 256 * i);
            CP_COMMIT();
        }
        CP_WAIT(1); __syncthreads();
        hh_chunk(hb1, whh + 1 * 160 * 16, acc, koff, r0, bq);
        __syncthreads();
        {
            const float4* s3 = (const float4*)(hsrc + 3 * 160 * 32);
#pragma unroll
            for (int i = 0; i < 5; ++i) cp16(hb_a[1] + (tid + 256 * i) * 16, s3 + tid + 256 * i);
            CP_COMMIT();
        }
        CP_WAIT(1); __syncthreads();
        hh_chunk(hb0, whh + 2 * 160 * 16, acc, koff, r0, bq);
        CP_WAIT(0); __syncthreads();
        hh_chunk(hb1, whh + 3 * 160 * 16, acc, koff, r0, bq);

        // reduce split-k within warp (kq), store per-kh partials
#pragma unroll
        for (int r = 0; r < 8; ++r) {
#pragma unroll
            for (int p = 0; p < 2; ++p) {
                unsigned long long v = acc[r][p];
                float2 f = *(float2*)&v;
                f.x += __shfl_xor_sync(0xffffffffu, f.x, 8);
                f.y += __shfl_xor_sync(0xffffffffu, f.y, 8);
                f.x += __shfl_xor_sync(0xffffffffu, f.x, 16);
                f.y += __shfl_xor_sync(0xffffffffu, f.y, 16);
                *(float2*)&acc[r][p] = f;
            }
        }
        if (lane < 8) {
#pragma unroll
            for (int r = 0; r < 8; ++r) {
                float2 a0 = *(float2*)&acc[r][0];
                float2 a1 = *(float2*)&acc[r][1];
                float4 o; o.x = a0.x; o.y = a0.y; o.z = a1.x; o.w = a1.y;
                *(float4*)&gacc[(kh * 16 + r0 + r) * 32 + 4 * bq] = o;
            }
        }
        __syncthreads();

        // pointwise GRU cell: 5 units x 32 batch
        if (pw) {
            int rr = pc, rz = 5 + pc, rn = 10 + pc;
            float xpr = xacc[rr*32+pb] + xacc[512+rr*32+pb] + xacc[1024+rr*32+pb] + xacc[1536+rr*32+pb] + bih[rr];
            float xpz = xacc[rz*32+pb] + xacc[512+rz*32+pb] + xacc[1024+rz*32+pb] + xacc[1536+rz*32+pb] + bih[rz];
            float xpn = xacc[rn*32+pb] + xacc[512+rn*32+pb] + xacc[1024+rn*32+pb] + xacc[1536+rn*32+pb] + bih[rn];
            float ghr = gacc[rr*32+pb] + gacc[512+rr*32+pb] + gacc[1024+rr*32+pb] + gacc[1536+rr*32+pb] + bhh[rr];
            float ghz = gacc[rz*32+pb] + gacc[512+rz*32+pb] + gacc[1024+rz*32+pb] + gacc[1536+rz*32+pb] + bhh[rz];
            float ghn = gacc[rn*32+pb] + gacc[512+rn*32+pb] + gacc[1024+rn*32+pb] + gacc[1536+rn*32+pb] + bhh[rn];
            float r = 1.f / (1.f + expf(-(xpr + ghr)));
            float z = 1.f / (1.f + expf(-(xpz + ghz)));
            float n = tanhf(xpn + r * ghn);
            float hnew = (1.f - z) * n + z * hold;
            __stcg(&d_hbuf[(t + 1) & 1][(j0 + pc) * BATCH + pb], hnew);
            hn[pc * 32 + pb] = hnew;
        }
        __syncthreads();
        if (tid < 32) {
            float fp = 0.f;
#pragma unroll
            for (int c = 0; c < 5; ++c) fp += hn[c * 32 + tid] * fcw[c];
            d_fcpart[((size_t)t * NB + bid) * 32 + tid] = fp;
        }
        // prefetch seq[t+1] (sbuf free; hidden behind barrier of next iter)
        if (t + 1 < T_LEN) {
            const float4* src = (const float4*)(d_seq + (size_t)(t + 1) * (HDIM * BATCH));
#pragma unroll
            for (int i = 0; i < 20; ++i)
                cp16(sbuf_a + (tid + 256 * i) * 16, src + tid + 256 * i);
            CP_COMMIT();
        }
    }
}

// ------------------- K7: fc reduction (deterministic) ----------------------
__global__ void k7_out(const float* __restrict__ fc_b, float* __restrict__ out) {
    int t = blockIdx.x;
    int b = threadIdx.x;   // 32 threads
    float s = fc_b[0];
    const float* p = d_fcpart + (size_t)t * NB * 32 + b;
#pragma unroll 16
    for (int i = 0; i < NB; ++i) s += p[i * 32];
    out[(size_t)b * T_LEN + t] = s;
}

// ------------------------- launch ------------------------------------------
extern "C" void kernel_launch(void* const* d_in, const int* in_sizes, int n_in,
                              void* d_out, int out_size) {
    const float* x        = (const float*)d_in[0];
    const float* a_vals   = (const float*)d_in[1];
    const float* w_vals   = (const float*)d_in[2];
    const float* dcls_w   = (const float*)d_in[3];
    const float* dcls_p   = (const float*)d_in[4];
    const float* dcls_b   = (const float*)d_in[5];
    const float* bn_gamma = (const float*)d_in[6];
    const float* bn_beta  = (const float*)d_in[7];
    const float* W_ih     = (const float*)d_in[8];
    const float* W_hh     = (const float*)d_in[9];
    const float* b_ih     = (const float*)d_in[10];
    const float* b_hh     = (const float*)d_in[11];
    const float* fc_w     = (const float*)d_in[12];
    const float* fc_b     = (const float*)d_in[13];
    float* out = (float*)d_out;

    cudaFuncSetAttribute(k3_dcls, cudaFuncAttributeMaxDynamicSharedMemorySize,
                         14 * 1012 * (int)sizeof(float));
    cudaFuncSetAttribute(k6_gru, cudaFuncAttributeMaxDynamicSharedMemorySize,
                         SM6_FLOATS * (int)sizeof(float));

    k1_highpass<<<dim3(BATCH, NF), 256>>>(x, a_vals, w_vals);
    k2_dk<<<(HDIM * 14 + 255) / 256, 256>>>(dcls_w, dcls_p);
    k3_dcls<<<dim3(10, BATCH), 256, 14 * 1012 * sizeof(float)>>>(dcls_b);
    k4a_stats<<<640, 256>>>();
    k4b_stats<<<1, 64>>>();
    k5_norm<<<HDIM, 256>>>(bn_gamma, bn_beta);
    k6_gru<<<NB, 256, SM6_FLOATS * sizeof(float)>>>(W_ih, W_hh, b_ih, b_hh, fc_w);
    k7_out<<<T_LEN, 32>>>(fc_b, out);
}